// round 1
// baseline (speedup 1.0000x reference)
#include <cuda_runtime.h>
#include <cstdint>
#include <math.h>

typedef unsigned long long ull;

#define B_    8
#define T_    1024
#define DL    1024
#define NH    8
#define DKH   128
#define DFF   2048
#define FH    256
#define MROWS (B_*T_)   /* 8192 */

// ---------------- scratch (device globals: allocation-free rule) ----------------
__device__ float g_H1[(size_t)MROWS*DFF];   // 64 MB
__device__ float g_X [(size_t)MROWS*DL];    // 32 MB
__device__ float g_Hn[(size_t)MROWS*DL];
__device__ float g_Q [(size_t)MROWS*DL];
__device__ float g_K [(size_t)MROWS*DL];
__device__ float g_V [(size_t)MROWS*DL];
__device__ float g_S [(size_t)B_*NH*T_*T_]; // 256 MB scores
__device__ float g_O [(size_t)MROWS*DL];
__device__ float g_F1[(size_t)MROWS*FH];

// ---------------- packed f32x2 helpers ----------------
__device__ __forceinline__ ull pack2(float x, float y){
    ull r; asm("mov.b64 %0, {%1,%2};" : "=l"(r) : "f"(x), "f"(y)); return r;
}
__device__ __forceinline__ void unpack2(ull v, float &x, float &y){
    asm("mov.b64 {%0,%1}, %2;" : "=f"(x), "=f"(y) : "l"(v));
}
__device__ __forceinline__ void ffma2(ull &c, ull a, ull b){
    asm("fma.rn.f32x2 %0, %1, %2, %0;" : "+l"(c) : "l"(a), "l"(b));
}

// ---------------- generic fp32 GEMM ----------------
// C[m,n] = alpha * sum_k A[m,k] * B'[k,n]  (+bias[n]) (relu) (+resid)
// NT=true : B is [N,K] row-major (B' = B^T), i.e. weights / K-major both sides
// NT=false: B is [K,N] row-major
// Batched via blockIdx.z with (z/batch2, z%batch2) offsets (b,h decomposition).
template<bool NT>
__global__ __launch_bounds__(256,2) void gemm_f32(
    const float* __restrict__ A, const float* __restrict__ Bm,
    float* __restrict__ C, const float* __restrict__ bias,
    const float* __restrict__ resid,
    int Kd, int lda, int ldb, int ldc,
    long long sA1, long long sA2, long long sB1, long long sB2,
    long long sC1, long long sC2,
    int batch2, float alpha, int relu)
{
    __shared__ float As[16][128];
    __shared__ float Bs[16][128];

    const int tid = threadIdx.x;
    const int z   = blockIdx.z;
    const int zb  = z / batch2;
    const int zh  = z - zb * batch2;

    const float* Ab = A + (size_t)zb*sA1 + (size_t)zh*sA2 + (size_t)blockIdx.y*128*lda;
    const float* Bb;
    if (NT) Bb = Bm + (size_t)zb*sB1 + (size_t)zh*sB2 + (size_t)blockIdx.x*128*ldb;
    else    Bb = Bm + (size_t)zb*sB1 + (size_t)zh*sB2 + (size_t)blockIdx.x*128;

    ull acc[8][4];
    #pragma unroll
    for (int i=0;i<8;i++)
        #pragma unroll
        for (int j=0;j<4;j++) acc[i][j] = 0ull;

    const int tr = (tid >> 4) << 3;   // 0..120, row in tile
    const int tc = (tid & 15) << 3;   // 0..120, col in tile

    for (int k0 = 0; k0 < Kd; k0 += 16) {
        #pragma unroll
        for (int i = 0; i < 2; i++) {
            int idx = tid*2 + i;                 // 0..511 float4 slots
            int r   = idx >> 2;                  // 0..127
            int c4  = (idx & 3) << 2;            // 0,4,8,12
            float4 v = *(const float4*)(Ab + (size_t)r*lda + k0 + c4);
            As[c4+0][r]=v.x; As[c4+1][r]=v.y; As[c4+2][r]=v.z; As[c4+3][r]=v.w;
            if (NT) {
                float4 w = *(const float4*)(Bb + (size_t)r*ldb + k0 + c4);
                Bs[c4+0][r]=w.x; Bs[c4+1][r]=w.y; Bs[c4+2][r]=w.z; Bs[c4+3][r]=w.w;
            } else {
                int rr = idx >> 5;               // 0..15
                int cc = (idx & 31) << 2;        // 0..124
                float4 w = *(const float4*)(Bb + (size_t)(k0+rr)*ldb + cc);
                *(float4*)&Bs[rr][cc] = w;
            }
        }
        __syncthreads();
        #pragma unroll
        for (int kk = 0; kk < 16; kk++) {
            float a[8];
            *(float4*)&a[0] = *(const float4*)&As[kk][tr];
            *(float4*)&a[4] = *(const float4*)&As[kk][tr+4];
            const float* bp = &Bs[kk][tc];
            ull b[4];
            b[0]=*(const ull*)(bp+0); b[1]=*(const ull*)(bp+2);
            b[2]=*(const ull*)(bp+4); b[3]=*(const ull*)(bp+6);
            #pragma unroll
            for (int i=0;i<8;i++){
                ull a2 = pack2(a[i], a[i]);
                #pragma unroll
                for (int j=0;j<4;j++) ffma2(acc[i][j], a2, b[j]);
            }
        }
        __syncthreads();
    }

    // ---- epilogue ----
    const size_t cbase = (size_t)zb*sC1 + (size_t)zh*sC2;
    const int row0 = blockIdx.y*128 + tr;
    const int col0 = blockIdx.x*128 + tc;
    float bv[8];
    #pragma unroll
    for (int j=0;j<8;j++) bv[j] = bias ? bias[col0+j] : 0.f;

    #pragma unroll
    for (int i=0;i<8;i++){
        float o[8];
        #pragma unroll
        for (int j=0;j<4;j++) unpack2(acc[i][j], o[2*j], o[2*j+1]);
        size_t roff = cbase + (size_t)(row0+i)*ldc + col0;
        #pragma unroll
        for (int j=0;j<8;j++){
            float v = o[j]*alpha + bv[j];
            if (relu) v = fmaxf(v, 0.f);
            o[j] = v;
        }
        if (resid) {
            float4 r0 = *(const float4*)(resid + roff);
            float4 r1 = *(const float4*)(resid + roff + 4);
            o[0]+=r0.x; o[1]+=r0.y; o[2]+=r0.z; o[3]+=r0.w;
            o[4]+=r1.x; o[5]+=r1.y; o[6]+=r1.z; o[7]+=r1.w;
        }
        float4 s0 = make_float4(o[0],o[1],o[2],o[3]);
        float4 s1 = make_float4(o[4],o[5],o[6],o[7]);
        *(float4*)(C + roff)     = s0;
        *(float4*)(C + roff + 4) = s1;
    }
}

// ---------------- LayerNorm: warp per row (D=1024, 32 floats/lane) ----------------
__global__ __launch_bounds__(128) void layernorm_k(
    const float* __restrict__ X, float* __restrict__ Y,
    const float* __restrict__ g, const float* __restrict__ b)
{
    const int row  = blockIdx.x*4 + (threadIdx.x >> 5);
    const int lane = threadIdx.x & 31;
    const float* p = X + (size_t)row*DL;

    float4 v[8];
    float s = 0.f;
    #pragma unroll
    for (int i=0;i<8;i++){
        v[i] = *(const float4*)(p + (i*32+lane)*4);
        s += v[i].x + v[i].y + v[i].z + v[i].w;
    }
    #pragma unroll
    for (int o=16;o>0;o>>=1) s += __shfl_xor_sync(0xffffffffu, s, o);
    const float m = s * (1.f/DL);

    float vs = 0.f;
    #pragma unroll
    for (int i=0;i<8;i++){
        float dx=v[i].x-m, dy=v[i].y-m, dz=v[i].z-m, dw=v[i].w-m;
        vs += dx*dx + dy*dy + dz*dz + dw*dw;
    }
    #pragma unroll
    for (int o=16;o>0;o>>=1) vs += __shfl_xor_sync(0xffffffffu, vs, o);
    const float r = rsqrtf(vs*(1.f/DL) + 1e-12f);

    float* q = Y + (size_t)row*DL;
    #pragma unroll
    for (int i=0;i<8;i++){
        int c = (i*32+lane)*4;
        float4 gg = *(const float4*)(g + c);
        float4 bb = *(const float4*)(b + c);
        float4 o;
        o.x = (v[i].x-m)*r*gg.x + bb.x;
        o.y = (v[i].y-m)*r*gg.y + bb.y;
        o.z = (v[i].z-m)*r*gg.z + bb.z;
        o.w = (v[i].w-m)*r*gg.w + bb.w;
        *(float4*)(q + c) = o;
    }
}

// ---------------- Softmax over rows of length 1024 (warp per row) ----------------
__global__ __launch_bounds__(128) void softmax_k(float* __restrict__ S)
{
    const int row  = blockIdx.x*4 + (threadIdx.x >> 5);
    const int lane = threadIdx.x & 31;
    float* p = S + (size_t)row*T_;

    float4 v[8];
    float mx = -INFINITY;
    #pragma unroll
    for (int i=0;i<8;i++){
        v[i] = *(const float4*)(p + (i*32+lane)*4);
        mx = fmaxf(mx, fmaxf(fmaxf(v[i].x,v[i].y), fmaxf(v[i].z,v[i].w)));
    }
    #pragma unroll
    for (int o=16;o>0;o>>=1) mx = fmaxf(mx, __shfl_xor_sync(0xffffffffu, mx, o));

    float s = 0.f;
    #pragma unroll
    for (int i=0;i<8;i++){
        v[i].x = __expf(v[i].x - mx);
        v[i].y = __expf(v[i].y - mx);
        v[i].z = __expf(v[i].z - mx);
        v[i].w = __expf(v[i].w - mx);
        s += v[i].x + v[i].y + v[i].z + v[i].w;
    }
    #pragma unroll
    for (int o=16;o>0;o>>=1) s += __shfl_xor_sync(0xffffffffu, s, o);
    const float inv = 1.f / s;

    #pragma unroll
    for (int i=0;i<8;i++){
        v[i].x*=inv; v[i].y*=inv; v[i].z*=inv; v[i].w*=inv;
        *(float4*)(p + (i*32+lane)*4) = v[i];
    }
}

// ---------------- host launch ----------------
static void launch_gemm(bool nt,
    const float*A, const float*B, float*C, const float*bias, const float*res,
    int M, int N, int Kd, int lda, int ldb, int ldc,
    long long sA1, long long sA2, long long sB1, long long sB2,
    long long sC1, long long sC2,
    int batch, int batch2, float alpha, int relu)
{
    dim3 grid(N/128, M/128, batch);
    dim3 blk(256);
    if (nt)
        gemm_f32<true ><<<grid,blk>>>(A,B,C,bias,res,Kd,lda,ldb,ldc,
                                      sA1,sA2,sB1,sB2,sC1,sC2,batch2,alpha,relu);
    else
        gemm_f32<false><<<grid,blk>>>(A,B,C,bias,res,Kd,lda,ldb,ldc,
                                      sA1,sA2,sB1,sB2,sC1,sC2,batch2,alpha,relu);
}

extern "C" void kernel_launch(void* const* d_in, const int* in_sizes, int n_in,
                              void* d_out, int out_size)
{
    (void)in_sizes; (void)n_in; (void)out_size;
    const float* x   = (const float*)d_in[0];
    const float* W1  = (const float*)d_in[1];
    const float* b1  = (const float*)d_in[2];
    const float* W2  = (const float*)d_in[3];
    const float* b2  = (const float*)d_in[4];
    const float* ln1g= (const float*)d_in[5];
    const float* ln1b= (const float*)d_in[6];
    const float* ln2g= (const float*)d_in[7];
    const float* ln2b= (const float*)d_in[8];
    const float* Wq  = (const float*)d_in[9];
    const float* bq  = (const float*)d_in[10];
    const float* Wk  = (const float*)d_in[11];
    const float* bk  = (const float*)d_in[12];
    const float* Wv  = (const float*)d_in[13];
    const float* bv  = (const float*)d_in[14];
    const float* Wo  = (const float*)d_in[15];
    const float* bo  = (const float*)d_in[16];
    const float* Fw1 = (const float*)d_in[17];
    const float* Fb1 = (const float*)d_in[18];
    const float* Fw2 = (const float*)d_in[19];
    const float* Fb2 = (const float*)d_in[20];
    float* out = (float*)d_out;

    float *H1,*X,*Hn,*Q,*Km,*V,*S,*O,*F1;
    cudaGetSymbolAddress((void**)&H1, g_H1);
    cudaGetSymbolAddress((void**)&X , g_X );
    cudaGetSymbolAddress((void**)&Hn, g_Hn);
    cudaGetSymbolAddress((void**)&Q , g_Q );
    cudaGetSymbolAddress((void**)&Km, g_K );
    cudaGetSymbolAddress((void**)&V , g_V );
    cudaGetSymbolAddress((void**)&S , g_S );
    cudaGetSymbolAddress((void**)&O , g_O );
    cudaGetSymbolAddress((void**)&F1, g_F1);

    const float scl = 0.08838834764831845f;  // DK^-0.5, DK=128

    // downsample: x[8192,1024] -> relu(xW1^T+b1)[8192,2048] -> W2^T+b2 -> X[8192,1024]
    launch_gemm(true, x,  W1, H1, b1, nullptr, MROWS, DFF, DL,  DL,  DL,  DFF,
                0,0,0,0,0,0, 1,1, 1.f, 1);
    launch_gemm(true, H1, W2, X,  b2, nullptr, MROWS, DL,  DFF, DFF, DFF, DL,
                0,0,0,0,0,0, 1,1, 1.f, 0);

    for (int l = 0; l < 2; l++) {
        const long long lw = (long long)l*DL*DL;
        // LN1
        layernorm_k<<<MROWS/4,128>>>(X, Hn, ln1g + l*DL, ln1b + l*DL);
        // QKV
        launch_gemm(true, Hn, Wq+lw, Q,  bq+l*DL, nullptr, MROWS, DL, DL, DL, DL, DL,
                    0,0,0,0,0,0, 1,1, 1.f, 0);
        launch_gemm(true, Hn, Wk+lw, Km, bk+l*DL, nullptr, MROWS, DL, DL, DL, DL, DL,
                    0,0,0,0,0,0, 1,1, 1.f, 0);
        launch_gemm(true, Hn, Wv+lw, V,  bv+l*DL, nullptr, MROWS, DL, DL, DL, DL, DL,
                    0,0,0,0,0,0, 1,1, 1.f, 0);
        // scores[b,h] = scl * Q_bh @ K_bh^T   (batched 64, z=(b*8+h))
        launch_gemm(true, Q, Km, S, nullptr, nullptr, T_, T_, DKH, DL, DL, T_,
                    (long long)T_*DL, DKH, (long long)T_*DL, DKH,
                    (long long)NH*T_*T_, (long long)T_*T_,
                    B_*NH, NH, scl, 0);
        softmax_k<<<(B_*NH*T_)/4,128>>>(S);
        // O[b,h] = attn @ V_bh   (NN)
        launch_gemm(false, S, V, O, nullptr, nullptr, T_, DKH, T_, T_, DL, DL,
                    (long long)NH*T_*T_, (long long)T_*T_,
                    (long long)T_*DL, DKH,
                    (long long)T_*DL, DKH,
                    B_*NH, NH, 1.f, 0);
        // X = X + O @ Wo^T + bo
        launch_gemm(true, O, Wo+lw, X, bo+l*DL, X, MROWS, DL, DL, DL, DL, DL,
                    0,0,0,0,0,0, 1,1, 1.f, 0);
        // LN2
        layernorm_k<<<MROWS/4,128>>>(X, Hn, ln2g + l*DL, ln2b + l*DL);
        // FFN
        launch_gemm(true, Hn, Fw1 + (long long)l*FH*DL, F1, Fb1 + l*FH, nullptr,
                    MROWS, FH, DL, DL, DL, FH, 0,0,0,0,0,0, 1,1, 1.f, 1);
        float* dst = (l == 1) ? out : X;
        launch_gemm(true, F1, Fw2 + (long long)l*DL*FH, dst, Fb2 + l*DL, X,
                    MROWS, DL, FH, FH, FH, DL, 0,0,0,0,0,0, 1,1, 1.f, 0);
    }
}